// round 6
// baseline (speedup 1.0000x reference)
#include <cuda_runtime.h>
#include <cuda_bf16.h>
#include <cstdint>

// BahdanauAttention with size-1 attention axis:
//   softmax over length-1 axis == 1.0 -> attention_weights = ones
//   context = features (bit-exact copy). Score GEMMs are dead code.
// Pure HBM streaming copy: 128 MiB read + 128 MiB write + 64 KiB fill.
//
// This round: test MLP=16 (all 16 loads front-batched before any store).
// MLP 4->8 bought 4.6us in round 3; this checks whether exposed DRAM
// latency is still the residual, or we've hit the R/W-turnaround floor.

static constexpr int Bsz = 16384;
static constexpr int Dsz = 2048;
static constexpr int CTX_VECS = (Bsz * Dsz) / 4;   // 8,388,608 float4 (2^23)
static constexpr int AW_VECS  = Bsz / 4;           // 4,096 float4

static constexpr int THREADS = 256;
static constexpr int BLOCKS  = 2048;
static constexpr int NTHREADS = THREADS * BLOCKS;           // 524,288 = 2^19
static constexpr int VECS_PER_THREAD = CTX_VECS / NTHREADS; // 16, exact

__global__ void __launch_bounds__(THREADS)
bahdanau_copy_kernel(const float4* __restrict__ features, float4* __restrict__ out) {
    int tid = blockIdx.x * THREADS + threadIdx.x;

    // All 16 loads issued before any store: MLP=16 per thread.
    float4 a[VECS_PER_THREAD];
    #pragma unroll
    for (int j = 0; j < VECS_PER_THREAD; j++)
        a[j] = features[tid + j * NTHREADS];
    #pragma unroll
    for (int j = 0; j < VECS_PER_THREAD; j++)
        out[tid + j * NTHREADS] = a[j];

    // Trailing ones for attention_weights: one extra store for 4096 threads.
    if (tid < AW_VECS) {
        out[CTX_VECS + tid] = make_float4(1.f, 1.f, 1.f, 1.f);
    }
}

extern "C" void kernel_launch(void* const* d_in, const int* in_sizes, int n_in,
                              void* d_out, int out_size) {
    const float4* features = (const float4*)d_in[0];
    float4* out = (float4*)d_out;
    bahdanau_copy_kernel<<<BLOCKS, THREADS>>>(features, out);
}

// round 7
// speedup vs baseline: 1.0170x; 1.0170x over previous
#include <cuda_runtime.h>
#include <cuda_bf16.h>
#include <cstdint>

// BahdanauAttention with size-1 attention axis:
//   softmax over length-1 axis == 1.0 -> attention_weights = ones
//   context = features (bit-exact copy). Score GEMMs are dead code.
// Pure HBM streaming copy: 128 MiB read + 128 MiB write + 64 KiB fill.
//
// Round 6 found ptxas silently rewrote the MLP=16 front-batch to fit a
// 32-reg budget. This round grants the budget: __launch_bounds__(256, 2)
// allows ~128 regs/thread so all 16 loads are genuinely in flight before
// the first store. Occupancy drop is harmless (in-flight bytes >> needed).

static constexpr int Bsz = 16384;
static constexpr int Dsz = 2048;
static constexpr int CTX_VECS = (Bsz * Dsz) / 4;   // 8,388,608 float4 (2^23)
static constexpr int AW_VECS  = Bsz / 4;           // 4,096 float4

static constexpr int THREADS = 256;
static constexpr int BLOCKS  = 2048;
static constexpr int NTHREADS = THREADS * BLOCKS;           // 524,288 = 2^19
static constexpr int VECS_PER_THREAD = CTX_VECS / NTHREADS; // 16, exact

__global__ void __launch_bounds__(THREADS, 2)
bahdanau_copy_kernel(const float4* __restrict__ features, float4* __restrict__ out) {
    int tid = blockIdx.x * THREADS + threadIdx.x;

    // All 16 loads issued before any store: true MLP=16 per thread.
    float4 a[VECS_PER_THREAD];
    #pragma unroll
    for (int j = 0; j < VECS_PER_THREAD; j++)
        a[j] = features[tid + j * NTHREADS];
    #pragma unroll
    for (int j = 0; j < VECS_PER_THREAD; j++)
        out[tid + j * NTHREADS] = a[j];

    // Trailing ones for attention_weights: one extra store for 4096 threads.
    if (tid < AW_VECS) {
        out[CTX_VECS + tid] = make_float4(1.f, 1.f, 1.f, 1.f);
    }
}

extern "C" void kernel_launch(void* const* d_in, const int* in_sizes, int n_in,
                              void* d_out, int out_size) {
    const float4* features = (const float4*)d_in[0];
    float4* out = (float4*)d_out;
    bahdanau_copy_kernel<<<BLOCKS, THREADS>>>(features, out);
}